// round 6
// baseline (speedup 1.0000x reference)
#include <cuda_runtime.h>
#include <cuda_fp16.h>
#include <cstdint>
#include <cstddef>

#define BH   32
#define SEQ  2048
#define DH   64
#define QB   64
#define KB   64
#define NQT  (SEQ/QB)      // 32
#define SK   72            // half stride
#define TSZ  (64*SK)
#define KA0_OFF 0
#define KA1_OFF (1*TSZ)
#define VA0_OFF (2*TSZ)
#define VA1_OFF (3*TSZ)
#define QS_OFF  (4*TSZ)
#define PF_OFF  (5*TSZ)    // P stage: 64 x 72 fp32 = 9216 floats (as halfs: 18432)
#define DYN_HALFS (5*TSZ + 64*72*2)   // 41472 halfs = 82944 B? -> recompute: 5*4608=23040 +9216*2/1... 
// 5*TSZ = 23040 halfs (46080B) + 18432 halfs (36864B)?? P stage is 64*72 floats = 18432B = 9216 halfs
#undef DYN_HALFS
#define DYN_HALFS (5*TSZ + 64*72*2)   // 23040 + 9216 = 32256 halfs = 64512 B
#define CEXP 0.180336880f  // log2(e)/8

__device__ __half g_qh[BH*SEQ*DH];
__device__ __half g_kh[BH*SEQ*DH];
__device__ __half g_vh[BH*SEQ*DH];

__device__ __forceinline__ uint32_t smem_u32(const void* p) {
    uint32_t a;
    asm("{ .reg .u64 t; cvta.to.shared.u64 t, %1; cvt.u32.u64 %0, t; }" : "=r"(a) : "l"(p));
    return a;
}
__device__ __forceinline__ void cpa16(uint32_t dst, const void* src) {
    asm volatile("cp.async.cg.shared.global [%0], [%1], 16;" :: "r"(dst), "l"(src));
}
#define CP_COMMIT() asm volatile("cp.async.commit_group;" ::: "memory")
#define CP_WAIT(n)  asm volatile("cp.async.wait_group %0;" :: "n"(n) : "memory")
__device__ __forceinline__ void ldm4(uint32_t* r, uint32_t addr) {
    asm volatile("ldmatrix.sync.aligned.m8n8.x4.shared.b16 {%0,%1,%2,%3}, [%4];"
        : "=r"(r[0]), "=r"(r[1]), "=r"(r[2]), "=r"(r[3]) : "r"(addr));
}
__device__ __forceinline__ void ldm4t(uint32_t* r, uint32_t addr) {
    asm volatile("ldmatrix.sync.aligned.m8n8.x4.trans.shared.b16 {%0,%1,%2,%3}, [%4];"
        : "=r"(r[0]), "=r"(r[1]), "=r"(r[2]), "=r"(r[3]) : "r"(addr));
}
__device__ __forceinline__ void mma16816(float* c, const uint32_t* a, uint32_t b0, uint32_t b1) {
    asm volatile("mma.sync.aligned.m16n8k16.row.col.f32.f16.f16.f32 "
        "{%0,%1,%2,%3}, {%4,%5,%6,%7}, {%8,%9}, {%0,%1,%2,%3};"
        : "+f"(c[0]), "+f"(c[1]), "+f"(c[2]), "+f"(c[3])
        : "r"(a[0]), "r"(a[1]), "r"(a[2]), "r"(a[3]), "r"(b0), "r"(b1));
}
__device__ __forceinline__ float ex2a(float x) {
    float r; asm("ex2.approx.f32 %0, %1;" : "=f"(r) : "f"(x)); return r;
}
__device__ __forceinline__ void stg128_cs(float* p, float4 v) {
    asm volatile("st.global.cs.v4.f32 [%0], {%1,%2,%3,%4};"
        :: "l"(p), "f"(v.x), "f"(v.y), "f"(v.z), "f"(v.w) : "memory");
}
__device__ __forceinline__ void stg64_cs(float* p, float2 v) {
    asm volatile("st.global.cs.v2.f32 [%0], {%1,%2};" :: "l"(p), "f"(v.x), "f"(v.y) : "memory");
}
__device__ __forceinline__ uint2 f4h4(float4 t) {
    __half2 h0 = __floats2half2_rn(t.x, t.y);
    __half2 h1 = __floats2half2_rn(t.z, t.w);
    uint2 r; r.x = *(uint32_t*)&h0; r.y = *(uint32_t*)&h1; return r;
}

__global__ void cvt_kernel(const float4* __restrict__ q, const float4* __restrict__ k,
                           const float4* __restrict__ v) {
    int i = blockIdx.x * 256 + threadIdx.x;
    ((uint2*)g_qh)[i] = f4h4(q[i]);
    ((uint2*)g_kh)[i] = f4h4(k[i]);
    ((uint2*)g_vh)[i] = f4h4(v[i]);
}

__device__ __forceinline__ void load_tile(uint32_t sb, int off, const __half* src, int tid) {
    #pragma unroll
    for (int j = 0; j < 4; j++) {
        int idx = tid + j * 128;
        int row = idx >> 3, col8 = (idx & 7) << 3;
        cpa16(sb + (uint32_t)(off + row * SK + col8) * 2, src + row * DH + col8);
    }
}

__global__ __launch_bounds__(128, 3) void attn_mma(
    float* __restrict__ outg, float* __restrict__ attng)
{
    extern __shared__ __half sh[];
    float* pstage = (float*)(sh + PF_OFF);

    const int tid  = threadIdx.x;
    const int wm   = tid >> 5, lane = tid & 31;
    const int tq   = lane >> 2, tig = lane & 3;
    const int qt   = (NQT - 1) - blockIdx.x;
    const int bh   = blockIdx.y;
    const int nkb  = qt + 1;

    const __half* qh = g_qh + ((size_t)bh * SEQ + qt * QB) * DH;
    const __half* kh = g_kh + (size_t)bh * SEQ * DH;
    const __half* vh = g_vh + (size_t)bh * SEQ * DH;
    float* ag = attng + (size_t)bh * SEQ * SEQ + (size_t)(qt * QB) * SEQ;
    float* og = outg + ((size_t)bh * SEQ + qt * QB) * DH;

    const uint32_t sb = smem_u32(sh);

    load_tile(sb, QS_OFF, qh, tid); CP_COMMIT();
    load_tile(sb, KA0_OFF, kh, tid); CP_COMMIT();

    {   // zero strictly-upper prob region (streaming stores)
        int zc = SEQ - nkb * KB;
        if (zc > 0) {
            int zw = zc >> 2;
            float4 z = make_float4(0.f, 0.f, 0.f, 0.f);
            for (int i = tid; i < QB * zw; i += 128) {
                int r = i / zw, c = i % zw;
                stg128_cs(ag + (size_t)r * SEQ + nkb * KB + c * 4, z);
            }
        }
    }

    CP_WAIT(1);
    __syncthreads();
    uint32_t qa[4][4];
    {
        int rr = lane & 15, cc8 = (lane >> 4) << 3;
        #pragma unroll
        for (int kk = 0; kk < 4; kk++)
            ldm4(qa[kk], sb + (uint32_t)(QS_OFF + (wm * 16 + rr) * SK + kk * 16 + cc8) * 2);
    }

    float l_t[2] = {0.f, 0.f};

    // ================= Pass A: row sums l =================
    for (int kb = 0; kb < nkb; kb++) {
        if (kb + 1 < nkb) {
            load_tile(sb, ((kb + 1) & 1) ? KA1_OFF : KA0_OFF, kh + (size_t)(kb + 1) * KB * DH, tid);
            CP_COMMIT(); CP_WAIT(1);
        } else CP_WAIT(0);
        __syncthreads();
        const int kcur = (kb & 1) ? KA1_OFF : KA0_OFF;

        float s[8][4];
        #pragma unroll
        for (int b = 0; b < 8; b++)
            #pragma unroll
            for (int c = 0; c < 4; c++) s[b][c] = 0.f;
        #pragma unroll
        for (int nt = 0; nt < 8; nt++)
            #pragma unroll
            for (int kk = 0; kk < 4; kk++) {
                const uint32_t* bp =
                    (const uint32_t*)&sh[kcur + (nt * 8 + tq) * SK + kk * 16 + tig * 2];
                mma16816(s[nt], qa[kk], bp[0], bp[4]);
            }

        if (kb == nkb - 1) {
            #pragma unroll
            for (int h = 0; h < 2; h++) {
                int ig = qt * QB + wm * 16 + h * 8 + tq;
                float acc = 0.f;
                #pragma unroll
                for (int nt = 0; nt < 8; nt++)
                    #pragma unroll
                    for (int c = 0; c < 2; c++) {
                        int jg = kb * KB + nt * 8 + tig * 2 + c;
                        float e = ex2a(s[nt][h * 2 + c] * CEXP);
                        acc += (jg <= ig) ? e : 0.f;
                    }
                l_t[h] += acc;
            }
        } else {
            #pragma unroll
            for (int h = 0; h < 2; h++) {
                float acc = 0.f;
                #pragma unroll
                for (int nt = 0; nt < 8; nt++)
                    #pragma unroll
                    for (int c = 0; c < 2; c++)
                        acc += ex2a(s[nt][h * 2 + c] * CEXP);
                l_t[h] += acc;
            }
        }
        __syncthreads();
    }

    float inv[2];
    #pragma unroll
    for (int h = 0; h < 2; h++) {
        float l = l_t[h];
        l += __shfl_xor_sync(0xffffffffu, l, 1);
        l += __shfl_xor_sync(0xffffffffu, l, 2);
        inv[h] = 1.0f / l;
    }

    // ================= Pass B: probs (smem-staged coalesced) + O = P @ V ==========
    float o[8][4];
    #pragma unroll
    for (int b = 0; b < 8; b++)
        #pragma unroll
        for (int c = 0; c < 4; c++) o[b][c] = 0.f;

    load_tile(sb, KA0_OFF, kh, tid);
    load_tile(sb, VA0_OFF, vh, tid);
    CP_COMMIT();

    for (int kb = 0; kb < nkb; kb++) {
        if (kb + 1 < nkb) {
            int alt = (kb + 1) & 1;
            load_tile(sb, alt ? KA1_OFF : KA0_OFF, kh + (size_t)(kb + 1) * KB * DH, tid);
            load_tile(sb, alt ? VA1_OFF : VA0_OFF, vh + (size_t)(kb + 1) * KB * DH, tid);
            CP_COMMIT(); CP_WAIT(1);
        } else CP_WAIT(0);
        __syncthreads();   // also guards pstage reads of previous block done
        const int kcur = (kb & 1) ? KA1_OFF : KA0_OFF;
        const int vcur = (kb & 1) ? VA1_OFF : VA0_OFF;

        float s[8][4];
        #pragma unroll
        for (int b = 0; b < 8; b++)
            #pragma unroll
            for (int c = 0; c < 4; c++) s[b][c] = 0.f;
        #pragma unroll
        for (int nt = 0; nt < 8; nt++)
            #pragma unroll
            for (int kk = 0; kk < 4; kk++) {
                const uint32_t* bp =
                    (const uint32_t*)&sh[kcur + (nt * 8 + tq) * SK + kk * 16 + tig * 2];
                mma16816(s[nt], qa[kk], bp[0], bp[4]);
            }

        // exp -> stage fp32 probs in smem -> pack P fragments
        bool diag = (kb == nkb - 1);
        uint32_t ph[8][2];
        #pragma unroll
        for (int h = 0; h < 2; h++) {
            int il = wm * 16 + h * 8 + tq;
            int ig = qt * QB + il;
            #pragma unroll
            for (int nt = 0; nt < 8; nt++) {
                int jl = nt * 8 + tig * 2;
                float p0 = ex2a(s[nt][h * 2 + 0] * CEXP) * inv[h];
                float p1 = ex2a(s[nt][h * 2 + 1] * CEXP) * inv[h];
                if (diag) {
                    int jg = kb * KB + jl;
                    if (jg     > ig) p0 = 0.f;
                    if (jg + 1 > ig) p1 = 0.f;
                }
                *(float2*)(pstage + il * 72 + jl) = make_float2(p0, p1);
                __half2 hp = __floats2half2_rn(p0, p1);
                ph[nt][h] = *(uint32_t*)&hp;
            }
        }

        // O += P @ V (register fragments; independent of staging)
        {
            int rr = lane & 15, cc8 = (lane >> 4) << 3;
            #pragma unroll
            for (int kt = 0; kt < 4; kt++) {
                uint32_t a[4] = { ph[2*kt][0], ph[2*kt][1], ph[2*kt+1][0], ph[2*kt+1][1] };
                #pragma unroll
                for (int nc = 0; nc < 4; nc++) {
                    uint32_t bt[4];
                    ldm4t(bt, sb + (uint32_t)(vcur + (kt * 16 + rr) * SK + nc * 16 + cc8) * 2);
                    mma16816(o[nc * 2 + 0], a, bt[0], bt[1]);
                    mma16816(o[nc * 2 + 1], a, bt[2], bt[3]);
                }
            }
        }
        __syncthreads();   // stage visible to all; k/v smem reads complete

        // coalesced streaming prob stores: 2 rows x 256B per warp instruction
        #pragma unroll
        for (int j = 0; j < 8; j++) {
            int idx = tid + j * 128;
            int r = idx >> 4, c4 = (idx & 15) << 2;
            float4 t = *(const float4*)(pstage + r * 72 + c4);
            stg128_cs(ag + (size_t)r * SEQ + kb * KB + c4, t);
        }
    }

    // ---- store O ----
    #pragma unroll
    for (int nt = 0; nt < 8; nt++)
        #pragma unroll
        for (int h = 0; h < 2; h++) {
            int il = wm * 16 + h * 8 + tq;
            int jl = nt * 8 + tig * 2;
            stg64_cs(og + (size_t)il * DH + jl,
                     make_float2(o[nt][h * 2], o[nt][h * 2 + 1]));
        }
}

extern "C" void kernel_launch(void* const* d_in, const int* in_sizes, int n_in,
                              void* d_out, int out_size) {
    const float* q = (const float*)d_in[0];
    const float* k = (const float*)d_in[1];
    const float* v = (const float*)d_in[2];
    // d_in[3]: causal mask, handled analytically

    float* out  = (float*)d_out;
    float* attn = (float*)d_out + (size_t)BH * SEQ * DH;

    cvt_kernel<<<BH * SEQ * DH / 4 / 256, 256>>>((const float4*)q, (const float4*)k,
                                                 (const float4*)v);
    cudaFuncSetAttribute(attn_mma, cudaFuncAttributeMaxDynamicSharedMemorySize, DYN_HALFS * 2);
    attn_mma<<<dim3(NQT, BH), 128, DYN_HALFS * 2>>>(out, attn);
}

// round 7
// speedup vs baseline: 1.0684x; 1.0684x over previous
#include <cuda_runtime.h>
#include <cuda_fp16.h>
#include <cstdint>
#include <cstddef>

#define BH   32
#define SEQ  2048
#define DH   64
#define QB   64
#define KB   64
#define NQT  (SEQ/QB)      // 32
#define SK   72            // half stride
#define TSZ  (64*SK)
#define KA0_OFF 0
#define KA1_OFF (1*TSZ)
#define VA0_OFF (2*TSZ)
#define VA1_OFF (3*TSZ)
#define QS_OFF  (4*TSZ)
#define PF_OFF  (5*TSZ)    // P stage: 64 x 72 fp32
#define DYN_HALFS (5*TSZ + 64*72*2)   // 32256 halfs = 64512 B
#define CEXP 0.180336880f  // log2(e)/8

__device__ __half g_qh[BH*SEQ*DH];
__device__ __half g_kh[BH*SEQ*DH];
__device__ __half g_vh[BH*SEQ*DH];

__device__ __forceinline__ uint32_t smem_u32(const void* p) {
    uint32_t a;
    asm("{ .reg .u64 t; cvta.to.shared.u64 t, %1; cvt.u32.u64 %0, t; }" : "=r"(a) : "l"(p));
    return a;
}
__device__ __forceinline__ void cpa16(uint32_t dst, const void* src) {
    asm volatile("cp.async.cg.shared.global [%0], [%1], 16;" :: "r"(dst), "l"(src));
}
#define CP_COMMIT() asm volatile("cp.async.commit_group;" ::: "memory")
#define CP_WAIT(n)  asm volatile("cp.async.wait_group %0;" :: "n"(n) : "memory")
__device__ __forceinline__ void ldm4(uint32_t* r, uint32_t addr) {
    asm volatile("ldmatrix.sync.aligned.m8n8.x4.shared.b16 {%0,%1,%2,%3}, [%4];"
        : "=r"(r[0]), "=r"(r[1]), "=r"(r[2]), "=r"(r[3]) : "r"(addr));
}
__device__ __forceinline__ void ldm4t(uint32_t* r, uint32_t addr) {
    asm volatile("ldmatrix.sync.aligned.m8n8.x4.trans.shared.b16 {%0,%1,%2,%3}, [%4];"
        : "=r"(r[0]), "=r"(r[1]), "=r"(r[2]), "=r"(r[3]) : "r"(addr));
}
__device__ __forceinline__ void mma16816(float* c, const uint32_t* a, uint32_t b0, uint32_t b1) {
    asm volatile("mma.sync.aligned.m16n8k16.row.col.f32.f16.f16.f32 "
        "{%0,%1,%2,%3}, {%4,%5,%6,%7}, {%8,%9}, {%0,%1,%2,%3};"
        : "+f"(c[0]), "+f"(c[1]), "+f"(c[2]), "+f"(c[3])
        : "r"(a[0]), "r"(a[1]), "r"(a[2]), "r"(a[3]), "r"(b0), "r"(b1));
}
__device__ __forceinline__ float ex2a(float x) {
    float r; asm("ex2.approx.f32 %0, %1;" : "=f"(r) : "f"(x)); return r;
}
__device__ __forceinline__ void stg128_cs(float* p, float4 v) {
    asm volatile("st.global.cs.v4.f32 [%0], {%1,%2,%3,%4};"
        :: "l"(p), "f"(v.x), "f"(v.y), "f"(v.z), "f"(v.w) : "memory");
}
__device__ __forceinline__ void stg64_cs(float* p, float2 v) {
    asm volatile("st.global.cs.v2.f32 [%0], {%1,%2};" :: "l"(p), "f"(v.x), "f"(v.y) : "memory");
}
__device__ __forceinline__ uint2 f4h4(float4 t) {
    __half2 h0 = __floats2half2_rn(t.x, t.y);
    __half2 h1 = __floats2half2_rn(t.z, t.w);
    uint2 r; r.x = *(uint32_t*)&h0; r.y = *(uint32_t*)&h1; return r;
}

__global__ void cvt_kernel(const float4* __restrict__ q, const float4* __restrict__ k,
                           const float4* __restrict__ v) {
    int i = blockIdx.x * 256 + threadIdx.x;
    ((uint2*)g_qh)[i] = f4h4(q[i]);
    ((uint2*)g_kh)[i] = f4h4(k[i]);
    ((uint2*)g_vh)[i] = f4h4(v[i]);
}

__device__ __forceinline__ void load_tile(uint32_t sb, int off, const __half* src, int tid) {
    #pragma unroll
    for (int j = 0; j < 4; j++) {
        int idx = tid + j * 128;
        int row = idx >> 3, col8 = (idx & 7) << 3;
        cpa16(sb + (uint32_t)(off + row * SK + col8) * 2, src + row * DH + col8);
    }
}

// QK^T: S[8][4] += Q(16 rows) x K(64 rows)^T with ldmatrix-fed B fragments
__device__ __forceinline__ void qk_mma(float s[8][4], const uint32_t qa[4][4],
                                       uint32_t kfb) {
    #pragma unroll
    for (int ntp = 0; ntp < 4; ntp++)
        #pragma unroll
        for (int kk = 0; kk < 4; kk++) {
            uint32_t bb[4];
            ldm4(bb, kfb + (uint32_t)(ntp * 16 * SK + kk * 16) * 2);
            mma16816(s[2 * ntp + 0], qa[kk], bb[0], bb[1]);
            mma16816(s[2 * ntp + 1], qa[kk], bb[2], bb[3]);
        }
}

__global__ __launch_bounds__(128, 3) void attn_mma(
    float* __restrict__ outg, float* __restrict__ attng)
{
    extern __shared__ __half sh[];
    float* pstage = (float*)(sh + PF_OFF);

    const int tid  = threadIdx.x;
    const int wm   = tid >> 5, lane = tid & 31;
    const int tq   = lane >> 2, tig = lane & 3;
    const int qt   = (NQT - 1) - blockIdx.x;
    const int bh   = blockIdx.y;
    const int nkb  = qt + 1;

    const __half* qh = g_qh + ((size_t)bh * SEQ + qt * QB) * DH;
    const __half* kh = g_kh + (size_t)bh * SEQ * DH;
    const __half* vh = g_vh + (size_t)bh * SEQ * DH;
    float* ag = attng + (size_t)bh * SEQ * SEQ + (size_t)(qt * QB) * SEQ;
    float* og = outg + ((size_t)bh * SEQ + qt * QB) * DH;

    const uint32_t sb = smem_u32(sh);
    // per-lane base offset (halfs) for K-fragment ldmatrix:
    // row-in-pair-block = ((lane>>4)&1)*8 + (lane&7), k-half = ((lane>>3)&1)*8
    const uint32_t kfrag_lane =
        (uint32_t)((((lane >> 4) & 1) * 8 + (lane & 7)) * SK + ((lane >> 3) & 1) * 8);

    load_tile(sb, QS_OFF, qh, tid); CP_COMMIT();
    load_tile(sb, KA0_OFF, kh, tid); CP_COMMIT();

    {   // zero strictly-upper prob region (streaming stores)
        int zc = SEQ - nkb * KB;
        if (zc > 0) {
            int zw = zc >> 2;
            float4 z = make_float4(0.f, 0.f, 0.f, 0.f);
            for (int i = tid; i < QB * zw; i += 128) {
                int r = i / zw, c = i % zw;
                stg128_cs(ag + (size_t)r * SEQ + nkb * KB + c * 4, z);
            }
        }
    }

    CP_WAIT(1);
    __syncthreads();
    uint32_t qa[4][4];
    {
        int rr = lane & 15, cc8 = (lane >> 4) << 3;
        #pragma unroll
        for (int kk = 0; kk < 4; kk++)
            ldm4(qa[kk], sb + (uint32_t)(QS_OFF + (wm * 16 + rr) * SK + kk * 16 + cc8) * 2);
    }

    float l_t[2] = {0.f, 0.f};

    // ================= Pass A: row sums l =================
    for (int kb = 0; kb < nkb; kb++) {
        if (kb + 1 < nkb) {
            load_tile(sb, ((kb + 1) & 1) ? KA1_OFF : KA0_OFF, kh + (size_t)(kb + 1) * KB * DH, tid);
            CP_COMMIT(); CP_WAIT(1);
        } else CP_WAIT(0);
        __syncthreads();
        const uint32_t kfb = sb + (uint32_t)(((kb & 1) ? KA1_OFF : KA0_OFF) + kfrag_lane) * 2;

        float s[8][4];
        #pragma unroll
        for (int b = 0; b < 8; b++)
            #pragma unroll
            for (int c = 0; c < 4; c++) s[b][c] = 0.f;
        qk_mma(s, qa, kfb);

        if (kb == nkb - 1) {
            #pragma unroll
            for (int h = 0; h < 2; h++) {
                int ig = qt * QB + wm * 16 + h * 8 + tq;
                float acc = 0.f;
                #pragma unroll
                for (int nt = 0; nt < 8; nt++)
                    #pragma unroll
                    for (int c = 0; c < 2; c++) {
                        int jg = kb * KB + nt * 8 + tig * 2 + c;
                        float e = ex2a(s[nt][h * 2 + c] * CEXP);
                        acc += (jg <= ig) ? e : 0.f;
                    }
                l_t[h] += acc;
            }
        } else {
            #pragma unroll
            for (int h = 0; h < 2; h++) {
                float acc = 0.f;
                #pragma unroll
                for (int nt = 0; nt < 8; nt++)
                    #pragma unroll
                    for (int c = 0; c < 2; c++)
                        acc += ex2a(s[nt][h * 2 + c] * CEXP);
                l_t[h] += acc;
            }
        }
        __syncthreads();
    }

    float inv[2];
    #pragma unroll
    for (int h = 0; h < 2; h++) {
        float l = l_t[h];
        l += __shfl_xor_sync(0xffffffffu, l, 1);
        l += __shfl_xor_sync(0xffffffffu, l, 2);
        inv[h] = 1.0f / l;
    }

    // ================= Pass B: probs (smem-staged coalesced) + O = P @ V ==========
    float o[8][4];
    #pragma unroll
    for (int b = 0; b < 8; b++)
        #pragma unroll
        for (int c = 0; c < 4; c++) o[b][c] = 0.f;

    load_tile(sb, KA0_OFF, kh, tid);
    load_tile(sb, VA0_OFF, vh, tid);
    CP_COMMIT();

    for (int kb = 0; kb < nkb; kb++) {
        if (kb + 1 < nkb) {
            int alt = (kb + 1) & 1;
            load_tile(sb, alt ? KA1_OFF : KA0_OFF, kh + (size_t)(kb + 1) * KB * DH, tid);
            load_tile(sb, alt ? VA1_OFF : VA0_OFF, vh + (size_t)(kb + 1) * KB * DH, tid);
            CP_COMMIT(); CP_WAIT(1);
        } else CP_WAIT(0);
        __syncthreads();
        const uint32_t kfb = sb + (uint32_t)(((kb & 1) ? KA1_OFF : KA0_OFF) + kfrag_lane) * 2;
        const int vcur = (kb & 1) ? VA1_OFF : VA0_OFF;

        float s[8][4];
        #pragma unroll
        for (int b = 0; b < 8; b++)
            #pragma unroll
            for (int c = 0; c < 4; c++) s[b][c] = 0.f;
        qk_mma(s, qa, kfb);

        // exp -> stage fp32 probs in smem -> pack P fragments
        bool diag = (kb == nkb - 1);
        uint32_t ph[8][2];
        #pragma unroll
        for (int h = 0; h < 2; h++) {
            int il = wm * 16 + h * 8 + tq;
            int ig = qt * QB + il;
            #pragma unroll
            for (int nt = 0; nt < 8; nt++) {
                int jl = nt * 8 + tig * 2;
                float p0 = ex2a(s[nt][h * 2 + 0] * CEXP) * inv[h];
                float p1 = ex2a(s[nt][h * 2 + 1] * CEXP) * inv[h];
                if (diag) {
                    int jg = kb * KB + jl;
                    if (jg     > ig) p0 = 0.f;
                    if (jg + 1 > ig) p1 = 0.f;
                }
                *(float2*)(pstage + il * 72 + jl) = make_float2(p0, p1);
                __half2 hp = __floats2half2_rn(p0, p1);
                ph[nt][h] = *(uint32_t*)&hp;
            }
        }

        // O += P @ V (register fragments)
        {
            int rr = lane & 15, cc8 = (lane >> 4) << 3;
            #pragma unroll
            for (int kt = 0; kt < 4; kt++) {
                uint32_t a[4] = { ph[2*kt][0], ph[2*kt][1], ph[2*kt+1][0], ph[2*kt+1][1] };
                #pragma unroll
                for (int nc = 0; nc < 4; nc++) {
                    uint32_t bt[4];
                    ldm4t(bt, sb + (uint32_t)(vcur + (kt * 16 + rr) * SK + nc * 16 + cc8) * 2);
                    mma16816(o[nc * 2 + 0], a, bt[0], bt[1]);
                    mma16816(o[nc * 2 + 1], a, bt[2], bt[3]);
                }
            }
        }
        __syncthreads();   // stage visible; k/v smem reads complete

        // coalesced streaming prob stores
        #pragma unroll
        for (int j = 0; j < 8; j++) {
            int idx = tid + j * 128;
            int r = idx >> 4, c4 = (idx & 15) << 2;
            float4 t = *(const float4*)(pstage + r * 72 + c4);
            stg128_cs(ag + (size_t)r * SEQ + kb * KB + c4, t);
        }
    }

    // ---- store O ----
    #pragma unroll
    for (int nt = 0; nt < 8; nt++)
        #pragma unroll
        for (int h = 0; h < 2; h++) {
            int il = wm * 16 + h * 8 + tq;
            int jl = nt * 8 + tig * 2;
            stg64_cs(og + (size_t)il * DH + jl,
                     make_float2(o[nt][h * 2], o[nt][h * 2 + 1]));
        }
}

extern "C" void kernel_launch(void* const* d_in, const int* in_sizes, int n_in,
                              void* d_out, int out_size) {
    const float* q = (const float*)d_in[0];
    const float* k = (const float*)d_in[1];
    const float* v = (const float*)d_in[2];
    // d_in[3]: causal mask, handled analytically

    float* out  = (float*)d_out;
    float* attn = (float*)d_out + (size_t)BH * SEQ * DH;

    cvt_kernel<<<BH * SEQ * DH / 4 / 256, 256>>>((const float4*)q, (const float4*)k,
                                                 (const float4*)v);
    cudaFuncSetAttribute(attn_mma, cudaFuncAttributeMaxDynamicSharedMemorySize, DYN_HALFS * 2);
    attn_mma<<<dim3(NQT, BH), 128, DYN_HALFS * 2>>>(out, attn);
}